// round 13
// baseline (speedup 1.0000x reference)
#include <cuda_runtime.h>
#include <cuda_fp16.h>
#include <math.h>
#include <stdint.h>

#define NB   32
#define HH   32
#define LL   1024
#define CC   512
#define MM   4096
#define NLTOT (NB*LL)         // 32768 rows

#define GBM 128               // rows per stripe
#define NSTRIPE (NLTOT/GBM)   // 256
#define NQ 4                  // N-quarters per stripe
#define NJOBS (NSTRIPE*NQ)    // 1024 jobs
#define NT_PER_Q 8            // 128-col ntiles per quarter
#define KCHUNK 4              // K chunks of 128 fp8 bytes

// ---- scratch (device globals: allocation-free) ----
__device__ float g_inv[NLTOT];                          // inverse norms
__device__ float g_tmp[(size_t)NLTOT*CC];               // horizontal blur (normalized)
__device__ __align__(16) uint8_t g_e8[(size_t)NLTOT*CC];   // normalized fp8 *8
__device__ float g_simpos[NLTOT];
__device__ float g_psum[(size_t)NJOBS*GBM];             // per-job partial exp-sums
__device__ float g_partial[256];
__device__ int   g_is64;
__device__ unsigned int g_work;

// ---------------------------------------------------------------------------
// PTX helpers
// ---------------------------------------------------------------------------
__device__ __forceinline__ void cp16(uint32_t dst, const void* src) {
    asm volatile("cp.async.cg.shared.global [%0], [%1], 16;\n" :: "r"(dst), "l"(src));
}
__device__ __forceinline__ void cp_commit() { asm volatile("cp.async.commit_group;\n"); }
__device__ __forceinline__ void cp_wait0()  { asm volatile("cp.async.wait_group 0;\n"); }

__device__ __forceinline__ void ldsm_x4(uint32_t& r0, uint32_t& r1, uint32_t& r2, uint32_t& r3,
                                        uint32_t addr) {
    asm volatile("ldmatrix.sync.aligned.m8n8.x4.shared.b16 {%0,%1,%2,%3}, [%4];\n"
                 : "=r"(r0), "=r"(r1), "=r"(r2), "=r"(r3) : "r"(addr));
}
__device__ __forceinline__ void mma_fp8_h(uint32_t& d0, uint32_t& d1,
                                          uint32_t a0, uint32_t a1, uint32_t a2, uint32_t a3,
                                          uint32_t b0, uint32_t b1) {
    asm volatile("mma.sync.aligned.m16n8k32.row.col.f16.e4m3.e4m3.f16 "
                 "{%0,%1},{%2,%3,%4,%5},{%6,%7},{%0,%1};\n"
                 : "+r"(d0), "+r"(d1)
                 : "r"(a0), "r"(a1), "r"(a2), "r"(a3), "r"(b0), "r"(b1));
}
__device__ __forceinline__ uint32_t smem_u32(const void* p) {
    uint32_t a;
    asm("{ .reg .u64 t; cvta.to.shared.u64 t, %1; cvt.u32.u64 %0, t; }" : "=r"(a) : "l"(p));
    return a;
}
__device__ __forceinline__ uint32_t swz(uint32_t r, uint32_t kbyte) {
    return r * 128u + (kbyte ^ ((r & 7u) << 4));
}
__device__ __forceinline__ uint16_t f2e4m3x2(float hi, float lo) {
    uint16_t w;
    asm("cvt.rn.satfinite.e4m3x2.f32 %0, %1, %2;" : "=h"(w) : "f"(hi), "f"(lo));
    return w;
}

// ---------------------------------------------------------------------------
// 0) init: work counter + index-dtype probe
// ---------------------------------------------------------------------------
__global__ void k_flag_init() { g_is64 = 1; g_work = 0u; }
__global__ void k_flag_check(const long long* __restrict__ idx) {
    int i = blockIdx.x * blockDim.x + threadIdx.x;   // 0..2047 (16KB either way)
    long long v = idx[i];
    if (v < 0 || v >= NLTOT) atomicAnd(&g_is64, 0);
}

// ---------------------------------------------------------------------------
// 1) normalize -> inv norms + fp8*8 (no fp32 copy)
// ---------------------------------------------------------------------------
__global__ void k_normalize(const float* __restrict__ x) {
    int r = blockIdx.x;
    int t = threadIdx.x;                       // 128
    const float4* xin = (const float4*)(x + (size_t)r * CC);
    float4 v = xin[t];
    float s = v.x*v.x + v.y*v.y + v.z*v.z + v.w*v.w;
    #pragma unroll
    for (int o = 16; o > 0; o >>= 1) s += __shfl_down_sync(0xffffffffu, s, o);
    __shared__ float sw[4];
    if ((t & 31) == 0) sw[t >> 5] = s;
    __syncthreads();
    float tot = sw[0] + sw[1] + sw[2] + sw[3];
    float inv = 1.0f / fmaxf(sqrtf(tot), 1e-12f);
    if (t == 0) g_inv[r] = inv;
    float4 o4 = make_float4(v.x*inv, v.y*inv, v.z*inv, v.w*inv);
    uint16_t w0 = f2e4m3x2(o4.y * 8.f, o4.x * 8.f);
    uint16_t w1 = f2e4m3x2(o4.w * 8.f, o4.z * 8.f);
    ((uint32_t*)(g_e8 + (size_t)r * CC))[t] = (uint32_t)w0 | ((uint32_t)w1 << 16);
}

// ---------------------------------------------------------------------------
// 2) horizontal blur along j, taps |d|<=8; reads raw emb * shared inv
// ---------------------------------------------------------------------------
__global__ void k_hblur(const float* __restrict__ emb) {
    int b = blockIdx.x;                         // (n,i): rows b*32..b*32+31
    int c = threadIdx.x;                        // 512
    __shared__ float sinv[32];
    if (c < 32) sinv[c] = g_inv[b * 32 + c];
    float gtr[9];
    #pragma unroll
    for (int k = 0; k < 9; k++) gtr[k] = expf(-(float)(k * k) * 0.125f);
    __syncthreads();
    size_t base = (size_t)b * HH * CC + c;
    float v[32];
    #pragma unroll
    for (int jp = 0; jp < 32; jp++)
        v[jp] = emb[base + (size_t)jp * CC] * sinv[jp];
    #pragma unroll
    for (int j = 0; j < 32; j++) {
        float acc = 0.f;
        #pragma unroll
        for (int d = -8; d <= 8; d++) {
            int jp = j + d;
            if (jp >= 0 && jp < 32) acc += gtr[d < 0 ? -d : d] * v[jp];
        }
        g_tmp[base + (size_t)j * CC] = acc;
    }
}

// ---------------------------------------------------------------------------
// 3) vertical blur (|d|<=8) + sim_pos = (dot-1)/(S_i*S_j-1), truncated S
// ---------------------------------------------------------------------------
__global__ void k_vblur_simpos(const float* __restrict__ emb) {
    int b = blockIdx.x;
    int n = b >> 5, j = b & 31;
    int c = threadIdx.x;                        // 512
    float gtr[9];
    #pragma unroll
    for (int k = 0; k < 9; k++) gtr[k] = expf(-(float)(k * k) * 0.125f);
    __shared__ float sS[32], sinv[32];
    __shared__ float swr[32][17];
    if (c < 32) {
        sinv[c] = g_inv[n * LL + c * HH + j];
        float s = 0.f;
        for (int q = 0; q < 32; q++) {
            int d = c - q; if (d < 0) d = -d;
            if (d <= 8) s += gtr[d];
        }
        sS[c] = s;
    }
    __syncthreads();
    size_t base = ((size_t)n * LL + j) * CC + c;     // l = ip*32 + j
    float v[32];
    #pragma unroll
    for (int ip = 0; ip < 32; ip++) v[ip] = g_tmp[base + (size_t)(ip * HH) * CC];
    int lane = c & 31, wid = c >> 5;
    #pragma unroll
    for (int i = 0; i < 32; i++) {
        float acc = 0.f;
        #pragma unroll
        for (int d = -8; d <= 8; d++) {
            int ip = i + d;
            if (ip >= 0 && ip < 32) acc += gtr[d < 0 ? -d : d] * v[ip];
        }
        float p = acc * emb[base + (size_t)(i * HH) * CC] * sinv[i];
        #pragma unroll
        for (int o = 16; o > 0; o >>= 1) p += __shfl_down_sync(0xffffffffu, p, o);
        if (lane == 0) swr[i][wid] = p;
    }
    __syncthreads();
    if (c < 32) {
        float d = 0.f;
        #pragma unroll
        for (int w = 0; w < 16; w++) d += swr[c][w];
        float Z = sS[c] * sS[j] - 1.0f;
        g_simpos[n * LL + c * HH + j] = (d - 1.0f) / Z;
    }
}

// ---------------------------------------------------------------------------
// 4) FP8 (fp16-accum) tensor GEMM, persistent queue, INLINE gather for B.
//    fp32 expf epilogue (R10 form).
// ---------------------------------------------------------------------------
#define SMA_OFF 0                 // A: 4 chunks * 16384 = 65536
#define SMB_OFF 65536             // B: 2 bufs * 16384 = 32768
#define SMR_OFF 98304             // red: 128*4 floats = 2048
#define SMW_OFF 100352            // job broadcast (4B)
#define SM_DYN  100360

__global__ void __launch_bounds__(256, 2) k_gemm_lse(const int* __restrict__ idx32) {
    extern __shared__ char smraw[];
    const uint32_t sbase = smem_u32(smraw);
    const uint32_t As = sbase + SMA_OFF;
    const uint32_t Bs = sbase + SMB_OFF;
    float* red = (float*)(smraw + SMR_OFF);
    unsigned int* sjob = (unsigned int*)(smraw + SMW_OFF);

    const int tid  = threadIdx.x;
    const int lane = tid & 31;
    const int wid  = tid >> 5;
    const int wm   = wid >> 2;        // 0..1 : 64-row half
    const int wn   = wid & 3;         // 0..3 : 32-col slice
    const int istr = g_is64 ? 2 : 1;  // index element stride (int32 words)

    const uint32_t a_row = wm * 64 + (lane & 15);
    const uint32_t a_kb  = (uint32_t)(lane >> 4) * 16u;
    const uint32_t gq    = lane >> 3;
    const uint32_t b_row = wn * 32 + ((gq >> 1) * 8) + (lane & 7);
    const uint32_t b_kb  = (gq & 1) * 16u;

    for (;;) {
        if (tid == 0) *sjob = atomicAdd(&g_work, 1u);
        __syncthreads();
        const unsigned int job = *sjob;
        __syncthreads();
        if (job >= NJOBS) break;

        const int stripe = job >> 2;
        const int q      = job & 3;
        const int rowBase = stripe * GBM;

        // ---- prologue: A stripe (64KB) + first B tile (gather inline) ----
        #pragma unroll
        for (int u = 0; u < 16; u++) {
            int i = tid + u * 256;
            int c = i >> 10, rem = i & 1023;
            int r = rem >> 3, kc = rem & 7;
            cp16(As + (uint32_t)c * 16384u + swz(r, kc * 16),
                 g_e8 + ((size_t)(rowBase + r) * CC + c * 128 + kc * 16));
        }
        {
            int ntg = q * NT_PER_Q;
            #pragma unroll
            for (int u = 0; u < 4; u++) {
                int i = tid + u * 256;
                int r = i >> 3, kc = i & 7;
                int m = ntg * 128 + r;
                int rw = idx32[(size_t)m * istr];
                if (rw < 0) rw = 0; if (rw >= NLTOT) rw = NLTOT - 1;
                cp16(Bs + swz(r, kc * 16),
                     g_e8 + ((size_t)rw * CC + kc * 16));
            }
        }
        cp_commit();

        uint32_t hc[4][4][2];            // fp16x2 accumulators
        float thrSum[8];
        #pragma unroll
        for (int i = 0; i < 8; i++) thrSum[i] = 0.f;

        const int NITER = NT_PER_Q * KCHUNK;   // 32
        for (int it = 0; it < NITER; it++) {
            const int chunk = it & 3;
            const int cb = it & 1;

            cp_wait0();
            __syncthreads();

            if (it < NITER - 1) {
                int nx = it + 1;
                int nnt = q * NT_PER_Q + (nx >> 2), nch = nx & 3;
                int nb = nx & 1;
                #pragma unroll
                for (int u = 0; u < 4; u++) {
                    int i = tid + u * 256;
                    int r = i >> 3, kc = i & 7;
                    int m = nnt * 128 + r;
                    int rw = idx32[(size_t)m * istr];
                    if (rw < 0) rw = 0; if (rw >= NLTOT) rw = NLTOT - 1;
                    cp16(Bs + (uint32_t)nb * 16384u + swz(r, kc * 16),
                         g_e8 + ((size_t)rw * CC + nch * 128 + kc * 16));
                }
                cp_commit();
            }

            if (chunk == 0) {
                #pragma unroll
                for (int mt = 0; mt < 4; mt++)
                    #pragma unroll
                    for (int nt = 0; nt < 4; nt++) {
                        hc[mt][nt][0] = 0u; hc[mt][nt][1] = 0u;
                    }
            }

            const uint32_t Abase = As + (uint32_t)chunk * 16384u;
            const uint32_t Bbase = Bs + (uint32_t)cb * 16384u;
            #pragma unroll
            for (int k = 0; k < 4; k++) {
                uint32_t ar[4][4];
                #pragma unroll
                for (int mt = 0; mt < 4; mt++) {
                    uint32_t r = a_row + mt * 16;
                    uint32_t addr = Abase + r * 128u + ((k * 32 + a_kb) ^ ((r & 7u) << 4));
                    ldsm_x4(ar[mt][0], ar[mt][1], ar[mt][2], ar[mt][3], addr);
                }
                uint32_t br[4][2];
                #pragma unroll
                for (int p = 0; p < 2; p++) {
                    uint32_t r = b_row + p * 16;
                    uint32_t addr = Bbase + r * 128u + ((k * 32 + b_kb) ^ ((r & 7u) << 4));
                    uint32_t r0, r1, r2, r3;
                    ldsm_x4(r0, r1, r2, r3, addr);
                    br[p*2][0] = r0; br[p*2][1] = r1;
                    br[p*2+1][0] = r2; br[p*2+1][1] = r3;
                }
                #pragma unroll
                for (int mt = 0; mt < 4; mt++)
                    #pragma unroll
                    for (int nt = 0; nt < 4; nt++)
                        mma_fp8_h(hc[mt][nt][0], hc[mt][nt][1],
                                  ar[mt][0], ar[mt][1], ar[mt][2], ar[mt][3],
                                  br[nt][0], br[nt][1]);
            }

            if (chunk == 3) {
                // descale (inputs *8 each -> /64) then fp32 exp; logits <= 1
                #pragma unroll
                for (int mt = 0; mt < 4; mt++) {
                    float s0 = 0.f, s1 = 0.f;
                    #pragma unroll
                    for (int nt = 0; nt < 4; nt++) {
                        float2 f0 = __half22float2(*reinterpret_cast<__half2*>(&hc[mt][nt][0]));
                        float2 f1 = __half22float2(*reinterpret_cast<__half2*>(&hc[mt][nt][1]));
                        s0 += __expf(f0.x * 0.015625f) + __expf(f0.y * 0.015625f);
                        s1 += __expf(f1.x * 0.015625f) + __expf(f1.y * 0.015625f);
                    }
                    thrSum[mt*2 + 0] += s0;
                    thrSum[mt*2 + 1] += s1;
                }
            }
        }

        __syncthreads();
        #pragma unroll
        for (int mt = 0; mt < 4; mt++) {
            #pragma unroll
            for (int h = 0; h < 2; h++) {
                float v = thrSum[mt*2 + h];
                v += __shfl_xor_sync(0xffffffffu, v, 1);
                v += __shfl_xor_sync(0xffffffffu, v, 2);
                if ((lane & 3) == 0) {
                    int rloc = wm*64 + mt*16 + h*8 + (lane >> 2);
                    red[rloc * 4 + wn] = v;
                }
            }
        }
        __syncthreads();
        if (tid < 128) {
            float s = red[tid*4+0] + red[tid*4+1] + red[tid*4+2] + red[tid*4+3];
            g_psum[(size_t)job * GBM + tid] = s;
        }
        __syncthreads();
    }
}

// ---------------------------------------------------------------------------
// 5) combine quarters + per-row loss -> per-block partials
// ---------------------------------------------------------------------------
__global__ void k_combine() {
    int r = blockIdx.x * 128 + threadIdx.x;    // 256 blocks x 128 thr
    int stripe = r >> 7, rloc = r & 127;
    float s = 0.f;
    #pragma unroll
    for (int q = 0; q < 4; q++)
        s += g_psum[(size_t)((stripe << 2) | q) * GBM + rloc];
    float sp = g_simpos[r];
    float loss = logf(s + __expf(sp)) - sp;
    int lane = threadIdx.x & 31, wid = threadIdx.x >> 5;
    #pragma unroll
    for (int o = 16; o > 0; o >>= 1) loss += __shfl_down_sync(0xffffffffu, loss, o);
    __shared__ float sw[4];
    if (lane == 0) sw[wid] = loss;
    __syncthreads();
    if (threadIdx.x == 0)
        g_partial[blockIdx.x] = sw[0] + sw[1] + sw[2] + sw[3];
}

// ---------------------------------------------------------------------------
// 6) finalize: mean over rows
// ---------------------------------------------------------------------------
__global__ void k_final(float* __restrict__ out) {
    int t = threadIdx.x;                        // 256
    float v = g_partial[t];
    #pragma unroll
    for (int o = 16; o > 0; o >>= 1) v += __shfl_down_sync(0xffffffffu, v, o);
    __shared__ float sw[8];
    if ((t & 31) == 0) sw[t >> 5] = v;
    __syncthreads();
    if (t == 0) {
        float tot = 0.f;
        #pragma unroll
        for (int w = 0; w < 8; w++) tot += sw[w];
        out[0] = tot / (float)NLTOT;
    }
}

// ---------------------------------------------------------------------------
// Launch graph (capture-legal fork: s1 first WAITS an origin-stream event):
//   main: [evStart] -> normalize -> [evFork] -> wait(evFlag) -> GEMM
//            -> wait(evJoin) -> combine -> final
//   s1:   wait(evStart) -> flag_init -> flag_check -> [evFlag]
//            -> wait(evFork) -> hblur -> vblur -> [evJoin]
// ---------------------------------------------------------------------------
extern "C" void kernel_launch(void* const* d_in, const int* in_sizes, int n_in,
                              void* d_out, int out_size) {
    const float* emb = nullptr;
    const void*  idx = nullptr;
    for (int i = 0; i < n_in; i++) {
        if (in_sizes[i] == NLTOT * CC) emb = (const float*)d_in[i];
        else if (in_sizes[i] == MM)    idx = d_in[i];
    }
    float* out = (float*)d_out;

    static int smCount = 0;
    static cudaStream_t s1;
    static cudaEvent_t evStart, evFork, evJoin, evFlag;
    if (smCount == 0) {
        cudaDeviceGetAttribute(&smCount, cudaDevAttrMultiProcessorCount, 0);
        if (smCount <= 0) smCount = 148;
        cudaStreamCreateWithFlags(&s1, cudaStreamNonBlocking);
        cudaEventCreateWithFlags(&evStart, cudaEventDisableTiming);
        cudaEventCreateWithFlags(&evFork, cudaEventDisableTiming);
        cudaEventCreateWithFlags(&evJoin, cudaEventDisableTiming);
        cudaEventCreateWithFlags(&evFlag, cudaEventDisableTiming);
        cudaFuncSetAttribute(k_gemm_lse, cudaFuncAttributeMaxDynamicSharedMemorySize, SM_DYN);
    }
    const int gridP = 2 * smCount;   // persistent: 2 CTAs/SM

    // origin-stream fork point (required for capture legality)
    cudaEventRecord(evStart, 0);

    // side stream: probe (joins capture via evStart)
    cudaStreamWaitEvent(s1, evStart, 0);
    k_flag_init<<<1, 1, 0, s1>>>();
    k_flag_check<<<8, 256, 0, s1>>>((const long long*)idx);
    cudaEventRecord(evFlag, s1);

    // main stream: normalize
    k_normalize<<<NLTOT, 128>>>(emb);
    cudaEventRecord(evFork, 0);

    // side stream: blur chain (needs normalize; feeds only k_combine)
    cudaStreamWaitEvent(s1, evFork, 0);
    k_hblur<<<NB * HH, 512, 0, s1>>>(emb);
    k_vblur_simpos<<<NB * HH, 512, 0, s1>>>(emb);
    cudaEventRecord(evJoin, s1);

    // main stream: GEMM (needs normalize + probe; gather inlined)
    cudaStreamWaitEvent(0, evFlag, 0);
    k_gemm_lse<<<gridP, 256, SM_DYN>>>((const int*)idx);

    cudaStreamWaitEvent(0, evJoin, 0);
    k_combine<<<256, 128>>>();
    k_final<<<1, 256>>>(out);
}

// round 14
// speedup vs baseline: 1.0978x; 1.0978x over previous
#include <cuda_runtime.h>
#include <cuda_fp16.h>
#include <math.h>
#include <stdint.h>

#define NB   32
#define HH   32
#define LL   1024
#define CC   512
#define MM   4096
#define NLTOT (NB*LL)         // 32768 rows

#define GBM 128               // rows per stripe
#define NSTRIPE (NLTOT/GBM)   // 256
#define NQ 4                  // N-quarters per stripe
#define NJOBS (NSTRIPE*NQ)    // 1024 jobs
#define NT_PER_Q 8            // 128-col ntiles per quarter
#define KCHUNK 4              // K chunks of 128 fp8 bytes

// ---- scratch (device globals: allocation-free) ----
__device__ float g_e[(size_t)NLTOT*CC];                 // normalized fp32 (blur path)
__device__ float g_tmp[(size_t)NLTOT*CC];               // horizontal blur
__device__ __align__(16) uint8_t g_e8[(size_t)NLTOT*CC];   // normalized fp8 *8
__device__ __align__(16) uint8_t g_neg8[(size_t)MM*CC];    // negatives fp8 *8
__device__ float g_simpos[NLTOT];
__device__ float g_psum[(size_t)NJOBS*GBM];             // per-job partial exp-sums
__device__ float g_partial[256];
__device__ int   g_is64;
__device__ unsigned int g_work;

// ---------------------------------------------------------------------------
// PTX helpers
// ---------------------------------------------------------------------------
__device__ __forceinline__ void cp16(uint32_t dst, const void* src) {
    asm volatile("cp.async.cg.shared.global [%0], [%1], 16;\n" :: "r"(dst), "l"(src));
}
__device__ __forceinline__ void cp_commit() { asm volatile("cp.async.commit_group;\n"); }
__device__ __forceinline__ void cp_wait0()  { asm volatile("cp.async.wait_group 0;\n"); }

__device__ __forceinline__ void ldsm_x4(uint32_t& r0, uint32_t& r1, uint32_t& r2, uint32_t& r3,
                                        uint32_t addr) {
    asm volatile("ldmatrix.sync.aligned.m8n8.x4.shared.b16 {%0,%1,%2,%3}, [%4];\n"
                 : "=r"(r0), "=r"(r1), "=r"(r2), "=r"(r3) : "r"(addr));
}
__device__ __forceinline__ void mma_fp8_h(uint32_t& d0, uint32_t& d1,
                                          uint32_t a0, uint32_t a1, uint32_t a2, uint32_t a3,
                                          uint32_t b0, uint32_t b1) {
    asm volatile("mma.sync.aligned.m16n8k32.row.col.f16.e4m3.e4m3.f16 "
                 "{%0,%1},{%2,%3,%4,%5},{%6,%7},{%0,%1};\n"
                 : "+r"(d0), "+r"(d1)
                 : "r"(a0), "r"(a1), "r"(a2), "r"(a3), "r"(b0), "r"(b1));
}
__device__ __forceinline__ uint32_t smem_u32(const void* p) {
    uint32_t a;
    asm("{ .reg .u64 t; cvta.to.shared.u64 t, %1; cvt.u32.u64 %0, t; }" : "=r"(a) : "l"(p));
    return a;
}
__device__ __forceinline__ uint32_t swz(uint32_t r, uint32_t kbyte) {
    return r * 128u + (kbyte ^ ((r & 7u) << 4));
}
__device__ __forceinline__ uint16_t f2e4m3x2(float hi, float lo) {
    uint16_t w;
    asm("cvt.rn.satfinite.e4m3x2.f32 %0, %1, %2;" : "=h"(w) : "f"(hi), "f"(lo));
    return w;
}

// ---------------------------------------------------------------------------
// 0) init: work counter + index-dtype probe
// ---------------------------------------------------------------------------
__global__ void k_flag_init() { g_is64 = 1; g_work = 0u; }
__global__ void k_flag_check(const long long* __restrict__ idx) {
    int i = blockIdx.x * blockDim.x + threadIdx.x;   // 0..2047 (16KB either way)
    long long v = idx[i];
    if (v < 0 || v >= NLTOT) atomicAnd(&g_is64, 0);
}

// ---------------------------------------------------------------------------
// 1) normalize -> fp32 (blur path) + fp8*8 (GEMM path)
// ---------------------------------------------------------------------------
__global__ void k_normalize(const float* __restrict__ x) {
    int r = blockIdx.x;
    int t = threadIdx.x;                       // 128
    const float4* xin = (const float4*)(x + (size_t)r * CC);
    float4 v = xin[t];
    float s = v.x*v.x + v.y*v.y + v.z*v.z + v.w*v.w;
    #pragma unroll
    for (int o = 16; o > 0; o >>= 1) s += __shfl_down_sync(0xffffffffu, s, o);
    __shared__ float sw[4];
    if ((t & 31) == 0) sw[t >> 5] = s;
    __syncthreads();
    float tot = sw[0] + sw[1] + sw[2] + sw[3];
    float inv = 1.0f / fmaxf(sqrtf(tot), 1e-12f);
    float4 o4 = make_float4(v.x*inv, v.y*inv, v.z*inv, v.w*inv);
    ((float4*)(g_e + (size_t)r * CC))[t] = o4;
    uint16_t w0 = f2e4m3x2(o4.y * 8.f, o4.x * 8.f);
    uint16_t w1 = f2e4m3x2(o4.w * 8.f, o4.z * 8.f);
    ((uint32_t*)(g_e8 + (size_t)r * CC))[t] = (uint32_t)w0 | ((uint32_t)w1 << 16);
}

// ---------------------------------------------------------------------------
// 2) horizontal blur along j, taps truncated to |d|<=8 (dropped mass 8.8e-5)
// ---------------------------------------------------------------------------
__global__ void k_hblur() {
    int b = blockIdx.x;                         // (n,i)
    int c = threadIdx.x;                        // 512
    float gtr[9];
    #pragma unroll
    for (int k = 0; k < 9; k++) gtr[k] = expf(-(float)(k * k) * 0.125f);
    size_t base = (size_t)b * HH * CC + c;
    float v[32];
    #pragma unroll
    for (int jp = 0; jp < 32; jp++) v[jp] = g_e[base + (size_t)jp * CC];
    #pragma unroll
    for (int j = 0; j < 32; j++) {
        float acc = 0.f;
        #pragma unroll
        for (int d = -8; d <= 8; d++) {
            int jp = j + d;
            if (jp >= 0 && jp < 32) acc += gtr[d < 0 ? -d : d] * v[jp];
        }
        g_tmp[base + (size_t)j * CC] = acc;
    }
}

// ---------------------------------------------------------------------------
// 3) vertical blur (|d|<=8) + sim_pos = (dot-1)/(S_i*S_j-1), truncated S
// ---------------------------------------------------------------------------
__global__ void k_vblur_simpos() {
    int b = blockIdx.x;
    int n = b >> 5, j = b & 31;
    int c = threadIdx.x;                        // 512
    float gtr[9];
    #pragma unroll
    for (int k = 0; k < 9; k++) gtr[k] = expf(-(float)(k * k) * 0.125f);
    __shared__ float sS[32];
    __shared__ float swr[32][17];
    if (c < 32) {
        float s = 0.f;
        for (int q = 0; q < 32; q++) {
            int d = c - q; if (d < 0) d = -d;
            if (d <= 8) s += gtr[d];
        }
        sS[c] = s;
    }
    __syncthreads();
    size_t base = ((size_t)n * LL + j) * CC + c;     // l = ip*32 + j
    float v[32];
    #pragma unroll
    for (int ip = 0; ip < 32; ip++) v[ip] = g_tmp[base + (size_t)(ip * HH) * CC];
    int lane = c & 31, wid = c >> 5;
    #pragma unroll
    for (int i = 0; i < 32; i++) {
        float acc = 0.f;
        #pragma unroll
        for (int d = -8; d <= 8; d++) {
            int ip = i + d;
            if (ip >= 0 && ip < 32) acc += gtr[d < 0 ? -d : d] * v[ip];
        }
        float p = acc * g_e[base + (size_t)(i * HH) * CC];
        #pragma unroll
        for (int o = 16; o > 0; o >>= 1) p += __shfl_down_sync(0xffffffffu, p, o);
        if (lane == 0) swr[i][wid] = p;
    }
    __syncthreads();
    if (c < 32) {
        float d = 0.f;
        #pragma unroll
        for (int w = 0; w < 16; w++) d += swr[c][w];
        float Z = sS[c] * sS[j] - 1.0f;
        g_simpos[n * LL + c * HH + j] = (d - 1.0f) / Z;
    }
}

// ---------------------------------------------------------------------------
// 4) gather negatives (fp8) -> contiguous g_neg8
// ---------------------------------------------------------------------------
__global__ void k_gather(const int* __restrict__ idx32) {
    int m = blockIdx.x;
    int stride = g_is64 ? 2 : 1;
    int r = idx32[(size_t)m * stride];
    if (r < 0) r = 0; if (r >= NLTOT) r = NLTOT - 1;
    int t = threadIdx.x;                        // 32
    ((uint4*)(g_neg8 + (size_t)m * CC))[t] =
        ((const uint4*)(g_e8 + (size_t)r * CC))[t];
}

// ---------------------------------------------------------------------------
// 5) FP8 (fp16-accum) tensor GEMM, persistent queue; fp32 expf epilogue.
// ---------------------------------------------------------------------------
#define SMA_OFF 0                 // A: 4 chunks * 16384 = 65536
#define SMB_OFF 65536             // B: 2 bufs * 16384 = 32768
#define SMR_OFF 98304             // red: 128*4 floats = 2048
#define SMW_OFF 100352            // job broadcast (4B)
#define SM_DYN  100360

__global__ void __launch_bounds__(256, 2) k_gemm_lse() {
    extern __shared__ char smraw[];
    const uint32_t sbase = smem_u32(smraw);
    const uint32_t As = sbase + SMA_OFF;
    const uint32_t Bs = sbase + SMB_OFF;
    float* red = (float*)(smraw + SMR_OFF);
    unsigned int* sjob = (unsigned int*)(smraw + SMW_OFF);

    const int tid  = threadIdx.x;
    const int lane = tid & 31;
    const int wid  = tid >> 5;
    const int wm   = wid >> 2;        // 0..1 : 64-row half
    const int wn   = wid & 3;         // 0..3 : 32-col slice

    const uint32_t a_row = wm * 64 + (lane & 15);
    const uint32_t a_kb  = (uint32_t)(lane >> 4) * 16u;
    const uint32_t gq    = lane >> 3;
    const uint32_t b_row = wn * 32 + ((gq >> 1) * 8) + (lane & 7);
    const uint32_t b_kb  = (gq & 1) * 16u;

    for (;;) {
        if (tid == 0) *sjob = atomicAdd(&g_work, 1u);
        __syncthreads();
        const unsigned int job = *sjob;
        __syncthreads();
        if (job >= NJOBS) break;

        const int stripe = job >> 2;
        const int q      = job & 3;
        const int rowBase = stripe * GBM;

        // ---- prologue: A stripe (64KB) + first B tile ----
        #pragma unroll
        for (int u = 0; u < 16; u++) {
            int i = tid + u * 256;
            int c = i >> 10, rem = i & 1023;
            int r = rem >> 3, kc = rem & 7;
            cp16(As + (uint32_t)c * 16384u + swz(r, kc * 16),
                 g_e8 + ((size_t)(rowBase + r) * CC + c * 128 + kc * 16));
        }
        {
            int ntg = q * NT_PER_Q;
            #pragma unroll
            for (int u = 0; u < 4; u++) {
                int i = tid + u * 256;
                int r = i >> 3, kc = i & 7;
                cp16(Bs + swz(r, kc * 16),
                     g_neg8 + ((size_t)(ntg * 128 + r) * CC + kc * 16));
            }
        }
        cp_commit();

        uint32_t hc[4][4][2];            // fp16x2 accumulators
        float thrSum[8];
        #pragma unroll
        for (int i = 0; i < 8; i++) thrSum[i] = 0.f;

        const int NITER = NT_PER_Q * KCHUNK;   // 32
        for (int it = 0; it < NITER; it++) {
            const int chunk = it & 3;
            const int cb = it & 1;

            cp_wait0();
            __syncthreads();

            if (it < NITER - 1) {
                int nx = it + 1;
                int nnt = q * NT_PER_Q + (nx >> 2), nch = nx & 3;
                int nb = nx & 1;
                #pragma unroll
                for (int u = 0; u < 4; u++) {
                    int i = tid + u * 256;
                    int r = i >> 3, kc = i & 7;
                    cp16(Bs + (uint32_t)nb * 16384u + swz(r, kc * 16),
                         g_neg8 + ((size_t)(nnt * 128 + r) * CC + nch * 128 + kc * 16));
                }
                cp_commit();
            }

            if (chunk == 0) {
                #pragma unroll
                for (int mt = 0; mt < 4; mt++)
                    #pragma unroll
                    for (int nt = 0; nt < 4; nt++) {
                        hc[mt][nt][0] = 0u; hc[mt][nt][1] = 0u;
                    }
            }

            const uint32_t Abase = As + (uint32_t)chunk * 16384u;
            const uint32_t Bbase = Bs + (uint32_t)cb * 16384u;
            #pragma unroll
            for (int k = 0; k < 4; k++) {
                uint32_t ar[4][4];
                #pragma unroll
                for (int mt = 0; mt < 4; mt++) {
                    uint32_t r = a_row + mt * 16;
                    uint32_t addr = Abase + r * 128u + ((k * 32 + a_kb) ^ ((r & 7u) << 4));
                    ldsm_x4(ar[mt][0], ar[mt][1], ar[mt][2], ar[mt][3], addr);
                }
                uint32_t br[4][2];
                #pragma unroll
                for (int p = 0; p < 2; p++) {
                    uint32_t r = b_row + p * 16;
                    uint32_t addr = Bbase + r * 128u + ((k * 32 + b_kb) ^ ((r & 7u) << 4));
                    uint32_t r0, r1, r2, r3;
                    ldsm_x4(r0, r1, r2, r3, addr);
                    br[p*2][0] = r0; br[p*2][1] = r1;
                    br[p*2+1][0] = r2; br[p*2+1][1] = r3;
                }
                #pragma unroll
                for (int mt = 0; mt < 4; mt++)
                    #pragma unroll
                    for (int nt = 0; nt < 4; nt++)
                        mma_fp8_h(hc[mt][nt][0], hc[mt][nt][1],
                                  ar[mt][0], ar[mt][1], ar[mt][2], ar[mt][3],
                                  br[nt][0], br[nt][1]);
            }

            if (chunk == 3) {
                // descale (inputs *8 each -> /64) then fp32 exp; logits <= 1
                #pragma unroll
                for (int mt = 0; mt < 4; mt++) {
                    float s0 = 0.f, s1 = 0.f;
                    #pragma unroll
                    for (int nt = 0; nt < 4; nt++) {
                        float2 f0 = __half22float2(*reinterpret_cast<__half2*>(&hc[mt][nt][0]));
                        float2 f1 = __half22float2(*reinterpret_cast<__half2*>(&hc[mt][nt][1]));
                        s0 += __expf(f0.x * 0.015625f) + __expf(f0.y * 0.015625f);
                        s1 += __expf(f1.x * 0.015625f) + __expf(f1.y * 0.015625f);
                    }
                    thrSum[mt*2 + 0] += s0;
                    thrSum[mt*2 + 1] += s1;
                }
            }
        }

        __syncthreads();
        #pragma unroll
        for (int mt = 0; mt < 4; mt++) {
            #pragma unroll
            for (int h = 0; h < 2; h++) {
                float v = thrSum[mt*2 + h];
                v += __shfl_xor_sync(0xffffffffu, v, 1);
                v += __shfl_xor_sync(0xffffffffu, v, 2);
                if ((lane & 3) == 0) {
                    int rloc = wm*64 + mt*16 + h*8 + (lane >> 2);
                    red[rloc * 4 + wn] = v;
                }
            }
        }
        __syncthreads();
        if (tid < 128) {
            float s = red[tid*4+0] + red[tid*4+1] + red[tid*4+2] + red[tid*4+3];
            g_psum[(size_t)job * GBM + tid] = s;
        }
        __syncthreads();
    }
}

// ---------------------------------------------------------------------------
// 6) combine quarters + per-row loss -> per-block partials
// ---------------------------------------------------------------------------
__global__ void k_combine() {
    int r = blockIdx.x * 128 + threadIdx.x;    // 256 blocks x 128 thr
    int stripe = r >> 7, rloc = r & 127;
    float s = 0.f;
    #pragma unroll
    for (int q = 0; q < 4; q++)
        s += g_psum[(size_t)((stripe << 2) | q) * GBM + rloc];
    float sp = g_simpos[r];
    float loss = logf(s + __expf(sp)) - sp;
    int lane = threadIdx.x & 31, wid = threadIdx.x >> 5;
    #pragma unroll
    for (int o = 16; o > 0; o >>= 1) loss += __shfl_down_sync(0xffffffffu, loss, o);
    __shared__ float sw[4];
    if (lane == 0) sw[wid] = loss;
    __syncthreads();
    if (threadIdx.x == 0)
        g_partial[blockIdx.x] = sw[0] + sw[1] + sw[2] + sw[3];
}

// ---------------------------------------------------------------------------
// 7) finalize: mean over rows
// ---------------------------------------------------------------------------
__global__ void k_final(float* __restrict__ out) {
    int t = threadIdx.x;                        // 256
    float v = g_partial[t];
    #pragma unroll
    for (int o = 16; o > 0; o >>= 1) v += __shfl_down_sync(0xffffffffu, v, o);
    __shared__ float sw[8];
    if ((t & 31) == 0) sw[t >> 5] = v;
    __syncthreads();
    if (t == 0) {
        float tot = 0.f;
        #pragma unroll
        for (int w = 0; w < 8; w++) tot += sw[w];
        out[0] = tot / (float)NLTOT;
    }
}

// ---------------------------------------------------------------------------
// Launch graph (capture-legal fork via evStart):
//   main: [evStart] -> normalize -> [evFork] -> gather -> wait(evFlag) -> GEMM
//            -> wait(evJoin) -> combine -> final
//   s1:   wait(evStart) -> flag_init -> flag_check -> [evFlag]
//            -> wait(evFork) -> hblur -> vblur -> [evJoin]
// Note: gather reads g_is64 (probe result) -> main waits evFlag BEFORE gather.
// ---------------------------------------------------------------------------
extern "C" void kernel_launch(void* const* d_in, const int* in_sizes, int n_in,
                              void* d_out, int out_size) {
    const float* emb = nullptr;
    const void*  idx = nullptr;
    for (int i = 0; i < n_in; i++) {
        if (in_sizes[i] == NLTOT * CC) emb = (const float*)d_in[i];
        else if (in_sizes[i] == MM)    idx = d_in[i];
    }
    float* out = (float*)d_out;

    static int smCount = 0;
    static cudaStream_t s1;
    static cudaEvent_t evStart, evFork, evJoin, evFlag;
    if (smCount == 0) {
        cudaDeviceGetAttribute(&smCount, cudaDevAttrMultiProcessorCount, 0);
        if (smCount <= 0) smCount = 148;
        cudaStreamCreateWithFlags(&s1, cudaStreamNonBlocking);
        cudaEventCreateWithFlags(&evStart, cudaEventDisableTiming);
        cudaEventCreateWithFlags(&evFork, cudaEventDisableTiming);
        cudaEventCreateWithFlags(&evJoin, cudaEventDisableTiming);
        cudaEventCreateWithFlags(&evFlag, cudaEventDisableTiming);
        cudaFuncSetAttribute(k_gemm_lse, cudaFuncAttributeMaxDynamicSharedMemorySize, SM_DYN);
    }
    const int gridP = 2 * smCount;   // persistent: 2 CTAs/SM

    // origin-stream fork point (required for capture legality)
    cudaEventRecord(evStart, 0);

    // side stream: probe (overlaps normalize)
    cudaStreamWaitEvent(s1, evStart, 0);
    k_flag_init<<<1, 1, 0, s1>>>();
    k_flag_check<<<8, 256, 0, s1>>>((const long long*)idx);
    cudaEventRecord(evFlag, s1);

    // main stream: normalize
    k_normalize<<<NLTOT, 128>>>(emb);
    cudaEventRecord(evFork, 0);

    // side stream: blur chain (needs normalize; feeds only k_combine)
    cudaStreamWaitEvent(s1, evFork, 0);
    k_hblur<<<NB * HH, 512, 0, s1>>>();
    k_vblur_simpos<<<NB * HH, 512, 0, s1>>>();
    cudaEventRecord(evJoin, s1);

    // main stream: gather (needs probe result) + GEMM
    cudaStreamWaitEvent(0, evFlag, 0);
    k_gather<<<MM, 32>>>((const int*)idx);
    k_gemm_lse<<<gridP, 256, SM_DYN>>>();

    cudaStreamWaitEvent(0, evJoin, 0);
    k_combine<<<256, 128>>>();
    k_final<<<1, 256>>>(out);
}